// round 4
// baseline (speedup 1.0000x reference)
#include <cuda_runtime.h>
#include <cuda_bf16.h>
#include <cstdint>

// ---------------- problem constants ----------------
#define B_       2048
#define F_       7
#define CARD_    10000
#define E_       64
#define CONCAT_  256
#define NH_      512        // P_HID
#define KTOT_    65536      // CONCAT*CONCAT
#define KSPLIT_  4
#define KPER_    (KTOT_ / KSPLIT_)   // 16384
#define MT_      128
#define NT_      128
#define KC_      64

// c_s: [128][264] bf16 (pad 8 -> conflict-free), w_s: [64][136] bf16
#define CS_STRIDE 264
#define WS_STRIDE 136
#define CS_BYTES  (128 * CS_STRIDE * 2)
#define WS_BYTES  (64 * WS_STRIDE * 2)
#define SMEM_BYTES (CS_BYTES + WS_BYTES)   // 84992

// ---------------- device scratch (no allocation allowed) ----------------
__device__ alignas(256) __nv_bfloat16 g_Wb[(size_t)KTOT_ * NH_];       // 64 MB  bf16 pw1
__device__ alignas(256) __nv_bfloat16 g_Cb[(size_t)B_ * CONCAT_];      // 1 MB   bf16 concat
__device__ alignas(256) float         g_P[(size_t)KSPLIT_ * B_ * NH_]; // 16 MB  split-K partials

// ---------------- kernel 1: pw1 fp32 -> bf16 ----------------
__global__ void k_convert(const float4* __restrict__ src) {
    const size_t n4 = (size_t)KTOT_ * NH_ / 4;
    uint2* dst = reinterpret_cast<uint2*>(g_Wb);
    for (size_t i = (size_t)blockIdx.x * blockDim.x + threadIdx.x; i < n4;
         i += (size_t)gridDim.x * blockDim.x) {
        float4 v = src[i];
        __nv_bfloat162 lo = __floats2bfloat162_rn(v.x, v.y);
        __nv_bfloat162 hi = __floats2bfloat162_rn(v.z, v.w);
        uint2 o;
        o.x = *reinterpret_cast<unsigned*>(&lo);
        o.y = *reinterpret_cast<unsigned*>(&hi);
        dst[i] = o;
    }
}

// ---------------- kernel 2: feature MLPs -> c[b, 0:256] (bf16) ----------------
// one block per batch row, 64 threads.
// NOTE: sparse_features is int32 on device (JAX demotes int64 without x64 mode).
__global__ void k_features(const float* __restrict__ dense,
                           const int* __restrict__ sparse,
                           const float* __restrict__ emb,
                           const float* __restrict__ dw1, const float* __restrict__ db1,
                           const float* __restrict__ dw2, const float* __restrict__ db2,
                           const float* __restrict__ sw1, const float* __restrict__ sb1,
                           const float* __restrict__ sw2, const float* __restrict__ sb2) {
    const int b = blockIdx.x;
    const int t = threadIdx.x;
    __shared__ float sd[16];
    __shared__ float sh[64];
    __shared__ float se[64];

    if (t < 13) sd[t] = dense[b * 13 + t];
    __syncthreads();

    // dense layer 1: 13 -> 64, relu
    float h = db1[t];
#pragma unroll
    for (int d = 0; d < 13; d++) h += sd[d] * dw1[d * 64 + t];
    sh[t] = fmaxf(h, 0.f);
    __syncthreads();

    // dense layer 2: 64 -> 32
    if (t < 32) {
        float o = db2[t];
#pragma unroll
        for (int k = 0; k < 64; k++) o += sh[k] * dw2[k * 32 + t];
        g_Cb[(size_t)b * CONCAT_ + t] = __float2bfloat16(o);
    }

    // sparse features: tokenizers == arange(CARD) -> idx == raw value
    for (int f = 0; f < F_; f++) {
        __syncthreads();
        int idx = sparse[b * F_ + f];
        idx = min(max(idx, 0), CARD_ - 1);   // defensive: fault -> wrong-answer signal
        se[t] = emb[((size_t)f * CARD_ + idx) * E_ + t];
        __syncthreads();
        float hh = sb1[f * 64 + t];
#pragma unroll
        for (int e = 0; e < 64; e++) hh += se[e] * sw1[((size_t)f * 64 + e) * 64 + t];
        sh[t] = fmaxf(hh, 0.f);
        __syncthreads();
        if (t < 32) {
            float o = sb2[f * 32 + t];
#pragma unroll
            for (int k = 0; k < 64; k++) o += sh[k] * sw2[((size_t)f * 64 + k) * 32 + t];
            g_Cb[(size_t)b * CONCAT_ + 32 + f * 32 + t] = __float2bfloat16(o);
        }
    }
}

// ---------------- kernel 3: interaction GEMM (split-K, bf16 mma.sync) ----------------
// out_partial[ks][b][n] = sum_{k in ks-slice} (c[b,i]*c[b,j]) * Wb[k][n],  k = 256*i + j
__device__ __forceinline__ void mma16816(float* d, const unsigned* a, unsigned b0, unsigned b1) {
    asm volatile(
        "mma.sync.aligned.m16n8k16.row.col.f32.bf16.bf16.f32 "
        "{%0,%1,%2,%3}, {%4,%5,%6,%7}, {%8,%9}, {%0,%1,%2,%3};\n"
        : "+f"(d[0]), "+f"(d[1]), "+f"(d[2]), "+f"(d[3])
        : "r"(a[0]), "r"(a[1]), "r"(a[2]), "r"(a[3]), "r"(b0), "r"(b1));
}

__global__ void __launch_bounds__(256, 2) k_gemm() {
    extern __shared__ char smem[];
    __nv_bfloat16* c_s = reinterpret_cast<__nv_bfloat16*>(smem);             // [128][264]
    __nv_bfloat16* w_s = reinterpret_cast<__nv_bfloat16*>(smem + CS_BYTES);  // [64][136]

    const int tid  = threadIdx.x;
    const int lane = tid & 31;
    const int warp = tid >> 5;
    const int wm   = warp & 3;   // 4 warps along M (32 rows each)
    const int wn   = warp >> 2;  // 2 warps along N (64 cols each)
    const int g    = lane >> 2;
    const int tg   = lane & 3;

    const int mbase = blockIdx.x * MT_;
    const int nbase = blockIdx.y * NT_;
    const int ks    = blockIdx.z;

    // load c tile [128][256] bf16 into padded smem
    {
        const uint4* src = reinterpret_cast<const uint4*>(g_Cb + (size_t)mbase * CONCAT_);
        for (int i = tid; i < 128 * 32; i += 256) {
            int r = i >> 5, c = i & 31;
            *reinterpret_cast<uint4*>(c_s + r * CS_STRIDE + c * 8) = src[r * 32 + c];
        }
    }

    float acc[2][8][4];
#pragma unroll
    for (int a = 0; a < 2; a++)
#pragma unroll
        for (int b2 = 0; b2 < 8; b2++)
#pragma unroll
            for (int c2 = 0; c2 < 4; c2++) acc[a][b2][c2] = 0.f;

    // per-lane ldmatrix base address (shared-space bytes), for k-step 0 / n-group 0
    unsigned w_u32;
    {
        unsigned base = (unsigned)__cvta_generic_to_shared(w_s);
        int mat = lane >> 3, rl = lane & 7;
        int krow = ((mat & 1) << 3) + rl;           // mats 1,3 -> k+8
        int ncol = wn * 64 + ((mat >> 1) << 3);     // mats 2,3 -> n+8
        w_u32 = base + 2u * (krow * WS_STRIDE + ncol);
    }

    const int kbase0 = ks * KPER_;
    for (int chunk = 0; chunk < KPER_ / KC_; chunk++) {
        const int k0 = kbase0 + chunk * KC_;
        __syncthreads();
        // cooperative load W tile [64][128] bf16 (row k -> 16 uint4)
        {
            const uint4* wsrc =
                reinterpret_cast<const uint4*>(g_Wb + (size_t)k0 * NH_ + nbase);
#pragma unroll
            for (int it = 0; it < 4; it++) {
                int idx = tid + it * 256;
                int kr = idx >> 4, nc = idx & 15;
                *reinterpret_cast<uint4*>(w_s + kr * WS_STRIDE + nc * 8) = wsrc[kr * 64 + nc];
            }
        }
        __syncthreads();

        const int iidx = k0 >> 8;     // constant within 64-wide chunk
        const int j0   = k0 & 255;

        __nv_bfloat162 xx[2][2];
#pragma unroll
        for (int mt = 0; mt < 2; mt++) {
            int r1 = wm * 32 + mt * 16 + g;
            xx[mt][0] = __bfloat162bfloat162(c_s[r1 * CS_STRIDE + iidx]);
            xx[mt][1] = __bfloat162bfloat162(c_s[(r1 + 8) * CS_STRIDE + iidx]);
        }

#pragma unroll
        for (int ks16 = 0; ks16 < 4; ks16++) {
            const int jb = j0 + ks16 * 16;

            // B fragments: 4x ldmatrix.x4.trans covering k16 x n64
            unsigned bf[4][4];
#pragma unroll
            for (int ng = 0; ng < 4; ng++) {
                unsigned addr = w_u32 + 2u * (ks16 * 16 * WS_STRIDE + ng * 16);
                asm volatile(
                    "ldmatrix.sync.aligned.m8n8.x4.trans.shared.b16 {%0,%1,%2,%3}, [%4];\n"
                    : "=r"(bf[ng][0]), "=r"(bf[ng][1]), "=r"(bf[ng][2]), "=r"(bf[ng][3])
                    : "r"(addr));
            }

            // A fragments synthesized from c: A[r][kk] = c[r][i] * c[r][jb+kk]
            unsigned af[2][4];
#pragma unroll
            for (int mt = 0; mt < 2; mt++) {
                int r1 = wm * 32 + mt * 16 + g;
                const __nv_bfloat162* p1 =
                    reinterpret_cast<const __nv_bfloat162*>(c_s + r1 * CS_STRIDE + jb + 2 * tg);
                const __nv_bfloat162* p2 =
                    reinterpret_cast<const __nv_bfloat162*>(c_s + (r1 + 8) * CS_STRIDE + jb + 2 * tg);
                __nv_bfloat162 a0 = __hmul2(xx[mt][0], p1[0]);
                __nv_bfloat162 a1 = __hmul2(xx[mt][1], p2[0]);
                __nv_bfloat162 a2 = __hmul2(xx[mt][0], p1[4]);  // +8 cols
                __nv_bfloat162 a3 = __hmul2(xx[mt][1], p2[4]);
                af[mt][0] = *reinterpret_cast<unsigned*>(&a0);
                af[mt][1] = *reinterpret_cast<unsigned*>(&a1);
                af[mt][2] = *reinterpret_cast<unsigned*>(&a2);
                af[mt][3] = *reinterpret_cast<unsigned*>(&a3);
            }

#pragma unroll
            for (int mt = 0; mt < 2; mt++)
#pragma unroll
                for (int ng = 0; ng < 4; ng++) {
                    mma16816(acc[mt][2 * ng],     af[mt], bf[ng][0], bf[ng][1]);
                    mma16816(acc[mt][2 * ng + 1], af[mt], bf[ng][2], bf[ng][3]);
                }
        }
    }

    // epilogue: write fp32 partials (deterministic, no atomics)
#pragma unroll
    for (int mt = 0; mt < 2; mt++) {
        int r1 = mbase + wm * 32 + mt * 16 + g;
#pragma unroll
        for (int nn = 0; nn < 8; nn++) {
            int col = nbase + wn * 64 + nn * 8 + 2 * tg;
            float* dst = g_P + ((size_t)ks * B_ + r1) * NH_ + col;
            *reinterpret_cast<float2*>(dst) = make_float2(acc[mt][nn][0], acc[mt][nn][1]);
            *reinterpret_cast<float2*>(dst + (size_t)8 * NH_) =
                make_float2(acc[mt][nn][2], acc[mt][nn][3]);
        }
    }
}

// ---------------- kernel 4: reduce splits + bias + relu + pw2 + sigmoid ----------------
__global__ void k_finalize(const float* __restrict__ pb1, const float* __restrict__ pw2,
                           const float* __restrict__ pb2, float* __restrict__ out) {
    const int b = blockIdx.x;
    const int t = threadIdx.x;
    float local = 0.f;
    for (int n = t; n < NH_; n += 128) {
        size_t o = (size_t)b * NH_ + n;
        float v = g_P[o] + g_P[(size_t)1 * B_ * NH_ + o] + g_P[(size_t)2 * B_ * NH_ + o] +
                  g_P[(size_t)3 * B_ * NH_ + o];
        v = fmaxf(v + pb1[n], 0.f);
        local += v * pw2[n];
    }
#pragma unroll
    for (int off = 16; off; off >>= 1) local += __shfl_down_sync(0xffffffffu, local, off);
    __shared__ float red[4];
    if ((t & 31) == 0) red[t >> 5] = local;
    __syncthreads();
    if (t == 0) {
        float s = red[0] + red[1] + red[2] + red[3] + pb2[0];
        out[b] = 1.f / (1.f + expf(-s));
    }
}

// ---------------- launch ----------------
extern "C" void kernel_launch(void* const* d_in, const int* in_sizes, int n_in,
                              void* d_out, int out_size) {
    const float* dense  = (const float*)d_in[0];
    const int*   sparse = (const int*)d_in[1];   // int32 (JAX demotes int64)
    /* d_in[2] tokenizers == arange(CARD): identity, unused */
    const float* emb = (const float*)d_in[3];
    const float* dw1 = (const float*)d_in[4];
    const float* db1 = (const float*)d_in[5];
    const float* dw2 = (const float*)d_in[6];
    const float* db2 = (const float*)d_in[7];
    const float* sw1 = (const float*)d_in[8];
    const float* sb1 = (const float*)d_in[9];
    const float* sw2 = (const float*)d_in[10];
    const float* sb2 = (const float*)d_in[11];
    const float* pw1 = (const float*)d_in[12];
    const float* pb1 = (const float*)d_in[13];
    const float* pw2 = (const float*)d_in[14];
    const float* pb2 = (const float*)d_in[15];
    float* out = (float*)d_out;

    cudaFuncSetAttribute(k_gemm, cudaFuncAttributeMaxDynamicSharedMemorySize, SMEM_BYTES);

    k_convert<<<4096, 256>>>(reinterpret_cast<const float4*>(pw1));
    k_features<<<B_, 64>>>(dense, sparse, emb, dw1, db1, dw2, db2, sw1, sb1, sw2, sb2);
    k_gemm<<<dim3(B_ / MT_, NH_ / NT_, KSPLIT_), 256, SMEM_BYTES>>>();
    k_finalize<<<B_, 128>>>(pb1, pw2, pb2, out);
}

// round 6
// speedup vs baseline: 1.6408x; 1.6408x over previous
#include <cuda_runtime.h>
#include <cuda_bf16.h>
#include <cstdint>

// ---------------- problem constants ----------------
#define B_       2048
#define F_       7
#define CARD_    10000
#define E_       64
#define CONCAT_  256
#define NH_      512        // P_HID
#define NBLK_    2176       // # of k16 blocks in 16-aligned upper triangle
#define KSPLIT_  4
#define CHUNKS_PER_SPLIT_ 136   // 4 splits x 136 chunks x 4 blocks = 2176
#define MT_      128
#define NT_      128

// c_s: [128][264] bf16 (pad 8 -> conflict-free), w stage: [64][136] bf16
#define CS_STRIDE 264
#define WS_STRIDE 136
#define CS_BYTES  (128 * CS_STRIDE * 2)
#define WS_BYTES  (64 * WS_STRIDE * 2)
#define SMEM_BYTES (CS_BYTES + 2 * WS_BYTES)   // 102400 (2-stage W pipeline)

// ---------------- device scratch ----------------
__device__ alignas(256) __nv_bfloat16 g_Ws[(size_t)NBLK_ * 16 * NH_];  // 35.7 MB folded weights
__device__ alignas(256) __nv_bfloat16 g_Cb[(size_t)B_ * CONCAT_];      // 1 MB concat features
__device__ alignas(256) float         g_P[(size_t)KSPLIT_ * B_ * NH_]; // 16 MB split-K partials
__device__ uchar2 g_blk[NBLK_];   // per k16-block: (i, j0)

// decode block index t -> (i, j0).  Group g = i>>4 has 16*(16-g) blocks.
// FIXED: monotone prefix-sum scan (previous version kept testing with a
// partially-updated cum and misclassified e.g. t=250 into group 2).
__device__ __forceinline__ uchar2 blk_decode(int t) {
    int acc = 0, g = 0, cum = 0;
#pragma unroll
    for (int h = 0; h < 16; h++) {
        acc += 16 * (16 - h);               // prefix count through group h
        if (t >= acc) { g = h + 1; cum = acc; }
    }
    int r = t - cum;
    int per = 16 - g;               // j-blocks per row in this group
    int i = 16 * g + r / per;
    int j0 = 16 * (g + r % per);
    uchar2 o; o.x = (unsigned char)i; o.y = (unsigned char)j0;
    return o;
}

// ---------------- kernel 0: build block table ----------------
__global__ void k_blocks() {
    for (int t = threadIdx.x; t < NBLK_; t += blockDim.x) g_blk[t] = blk_decode(t);
}

// ---------------- kernel 1: fold pw1 -> Ws (bf16) ----------------
// Ws[(t*16+kk)][n]: i=blk[t].x, j=blk[t].y+kk
//   j< i : 0          (padded slot; pair handled in row j)
//   j==i : W[256i+i][n]
//   j> i : W[256i+j][n] + W[256j+i][n]
__global__ void k_convert(const float* __restrict__ pw1) {
    const int t = blockIdx.x;
    const int i = g_blk[t].x, j0 = g_blk[t].y;
    for (int idx = threadIdx.x; idx < 16 * NH_; idx += blockDim.x) {
        int kk = idx >> 9, n = idx & (NH_ - 1);
        int j = j0 + kk;
        float v = 0.f;
        if (j >= i) {
            v = pw1[((size_t)(i << 8) + j) * NH_ + n];
            if (j > i) v += pw1[((size_t)(j << 8) + i) * NH_ + n];
        }
        g_Ws[((size_t)t * 16 + kk) * NH_ + n] = __float2bfloat16(v);
    }
}

// ---------------- kernel 2: feature MLPs -> c[b, 0:256] (bf16) ----------------
__global__ void k_features(const float* __restrict__ dense,
                           const int* __restrict__ sparse,
                           const float* __restrict__ emb,
                           const float* __restrict__ dw1, const float* __restrict__ db1,
                           const float* __restrict__ dw2, const float* __restrict__ db2,
                           const float* __restrict__ sw1, const float* __restrict__ sb1,
                           const float* __restrict__ sw2, const float* __restrict__ sb2) {
    const int b = blockIdx.x;
    const int t = threadIdx.x;
    __shared__ float sd[16];
    __shared__ float sh[64];
    __shared__ float se[64];

    if (t < 13) sd[t] = dense[b * 13 + t];
    __syncthreads();

    float h = db1[t];
#pragma unroll
    for (int d = 0; d < 13; d++) h += sd[d] * dw1[d * 64 + t];
    sh[t] = fmaxf(h, 0.f);
    __syncthreads();

    if (t < 32) {
        float o = db2[t];
#pragma unroll
        for (int k = 0; k < 64; k++) o += sh[k] * dw2[k * 32 + t];
        g_Cb[(size_t)b * CONCAT_ + t] = __float2bfloat16(o);
    }

    for (int f = 0; f < F_; f++) {
        __syncthreads();
        int idx = sparse[b * F_ + f];
        idx = min(max(idx, 0), CARD_ - 1);
        se[t] = emb[((size_t)f * CARD_ + idx) * E_ + t];
        __syncthreads();
        float hh = sb1[f * 64 + t];
#pragma unroll
        for (int e = 0; e < 64; e++) hh += se[e] * sw1[((size_t)f * 64 + e) * 64 + t];
        sh[t] = fmaxf(hh, 0.f);
        __syncthreads();
        if (t < 32) {
            float o = sb2[f * 32 + t];
#pragma unroll
            for (int k = 0; k < 64; k++) o += sh[k] * sw2[((size_t)f * 64 + k) * 32 + t];
            g_Cb[(size_t)b * CONCAT_ + 32 + f * 32 + t] = __float2bfloat16(o);
        }
    }
}

// ---------------- kernel 3: triangular interaction GEMM ----------------
__device__ __forceinline__ void mma16816(float* d, const unsigned* a, unsigned b0, unsigned b1) {
    asm volatile(
        "mma.sync.aligned.m16n8k16.row.col.f32.bf16.bf16.f32 "
        "{%0,%1,%2,%3}, {%4,%5,%6,%7}, {%8,%9}, {%0,%1,%2,%3};\n"
        : "+f"(d[0]), "+f"(d[1]), "+f"(d[2]), "+f"(d[3])
        : "r"(a[0]), "r"(a[1]), "r"(a[2]), "r"(a[3]), "r"(b0), "r"(b1));
}

__device__ __forceinline__ void cp_async16(unsigned daddr, const void* src) {
    asm volatile("cp.async.cg.shared.global [%0], [%1], 16;\n" :: "r"(daddr), "l"(src));
}

// prefetch one W chunk (64 rows x 128 cols bf16) into stage
__device__ __forceinline__ void w_prefetch(unsigned wst_u32, int t0, int nbase, int tid) {
    const uint4* wsrc = reinterpret_cast<const uint4*>(g_Ws + (size_t)t0 * 16 * NH_ + nbase);
#pragma unroll
    for (int it = 0; it < 4; it++) {
        int idx = tid + it * 256;
        int kr = idx >> 4, nc = idx & 15;
        cp_async16(wst_u32 + kr * (WS_STRIDE * 2) + nc * 16, wsrc + kr * 64 + nc);
    }
}

__global__ void __launch_bounds__(256, 2) k_gemm() {
    extern __shared__ char smem[];
    __nv_bfloat16* c_s = reinterpret_cast<__nv_bfloat16*>(smem);            // [128][264]
    const unsigned w_base_u32 =
        (unsigned)__cvta_generic_to_shared(smem + CS_BYTES);                // 2 stages

    const int tid  = threadIdx.x;
    const int lane = tid & 31;
    const int warp = tid >> 5;
    const int wm   = warp & 3;
    const int wn   = warp >> 2;
    const int g    = lane >> 2;
    const int tg   = lane & 3;

    const int mbase = blockIdx.x * MT_;
    const int nbase = blockIdx.y * NT_;
    const int ks    = blockIdx.z;
    const int tch0  = ks * CHUNKS_PER_SPLIT_;    // chunk = 4 consecutive k16 blocks

    // load c tile [128][256] bf16 into padded smem
    {
        const uint4* src = reinterpret_cast<const uint4*>(g_Cb + (size_t)mbase * CONCAT_);
        for (int i = tid; i < 128 * 32; i += 256) {
            int r = i >> 5, c = i & 31;
            *reinterpret_cast<uint4*>(c_s + r * CS_STRIDE + c * 8) = src[r * 32 + c];
        }
    }

    float acc[2][8][4];
#pragma unroll
    for (int a = 0; a < 2; a++)
#pragma unroll
        for (int b2 = 0; b2 < 8; b2++)
#pragma unroll
            for (int c2 = 0; c2 < 4; c2++) acc[a][b2][c2] = 0.f;

    // per-lane ldmatrix offset within a W stage
    unsigned w_lane_off;
    {
        int mat = lane >> 3, rl = lane & 7;
        int krow = ((mat & 1) << 3) + rl;
        int ncol = wn * 64 + ((mat >> 1) << 3);
        w_lane_off = 2u * (krow * WS_STRIDE + ncol);
    }

    // stage 0 prefetch
    w_prefetch(w_base_u32, (tch0 + 0) * 4, nbase, tid);
    asm volatile("cp.async.commit_group;\n");

    for (int c = 0; c < CHUNKS_PER_SPLIT_; c++) {
        const int t0 = (tch0 + c) * 4;
        if (c + 1 < CHUNKS_PER_SPLIT_) {
            w_prefetch(w_base_u32 + ((c + 1) & 1) * WS_BYTES, (t0 + 4), nbase, tid);
            asm volatile("cp.async.commit_group;\n");
            asm volatile("cp.async.wait_group 1;\n");
        } else {
            asm volatile("cp.async.wait_group 0;\n");
        }
        __syncthreads();   // stage (c&1) ready; also covers c_s on first iter

        const unsigned wst = w_base_u32 + (c & 1) * WS_BYTES + w_lane_off;

#pragma unroll
        for (int ks16 = 0; ks16 < 4; ks16++) {
            const uchar2 bl = g_blk[t0 + ks16];
            const int ii = bl.x, jb = bl.y;

            // B fragments from stage
            unsigned bf[4][4];
#pragma unroll
            for (int ng = 0; ng < 4; ng++) {
                unsigned addr = wst + 2u * (ks16 * 16 * WS_STRIDE + ng * 16);
                asm volatile(
                    "ldmatrix.sync.aligned.m8n8.x4.trans.shared.b16 {%0,%1,%2,%3}, [%4];\n"
                    : "=r"(bf[ng][0]), "=r"(bf[ng][1]), "=r"(bf[ng][2]), "=r"(bf[ng][3])
                    : "r"(addr));
            }

            // A fragments: A[r][kk] = c[r][ii] * c[r][jb+kk]
            unsigned af[2][4];
#pragma unroll
            for (int mt = 0; mt < 2; mt++) {
                int r1 = wm * 32 + mt * 16 + g;
                __nv_bfloat162 x0 = __bfloat162bfloat162(c_s[r1 * CS_STRIDE + ii]);
                __nv_bfloat162 x1 = __bfloat162bfloat162(c_s[(r1 + 8) * CS_STRIDE + ii]);
                const __nv_bfloat162* p1 =
                    reinterpret_cast<const __nv_bfloat162*>(c_s + r1 * CS_STRIDE + jb + 2 * tg);
                const __nv_bfloat162* p2 =
                    reinterpret_cast<const __nv_bfloat162*>(c_s + (r1 + 8) * CS_STRIDE + jb + 2 * tg);
                __nv_bfloat162 a0 = __hmul2(x0, p1[0]);
                __nv_bfloat162 a1 = __hmul2(x1, p2[0]);
                __nv_bfloat162 a2 = __hmul2(x0, p1[4]);
                __nv_bfloat162 a3 = __hmul2(x1, p2[4]);
                af[mt][0] = *reinterpret_cast<unsigned*>(&a0);
                af[mt][1] = *reinterpret_cast<unsigned*>(&a1);
                af[mt][2] = *reinterpret_cast<unsigned*>(&a2);
                af[mt][3] = *reinterpret_cast<unsigned*>(&a3);
            }

#pragma unroll
            for (int mt = 0; mt < 2; mt++)
#pragma unroll
                for (int ng = 0; ng < 4; ng++) {
                    mma16816(acc[mt][2 * ng],     af[mt], bf[ng][0], bf[ng][1]);
                    mma16816(acc[mt][2 * ng + 1], af[mt], bf[ng][2], bf[ng][3]);
                }
        }
        __syncthreads();   // all warps done with stage (c&1) before it is re-filled
    }

    // epilogue: deterministic fp32 partials
#pragma unroll
    for (int mt = 0; mt < 2; mt++) {
        int r1 = mbase + wm * 32 + mt * 16 + g;
#pragma unroll
        for (int nn = 0; nn < 8; nn++) {
            int col = nbase + wn * 64 + nn * 8 + 2 * tg;
            float* dst = g_P + ((size_t)ks * B_ + r1) * NH_ + col;
            *reinterpret_cast<float2*>(dst) = make_float2(acc[mt][nn][0], acc[mt][nn][1]);
            *reinterpret_cast<float2*>(dst + (size_t)8 * NH_) =
                make_float2(acc[mt][nn][2], acc[mt][nn][3]);
        }
    }
}

// ---------------- kernel 4: reduce splits + bias + relu + pw2 + sigmoid ----------------
__global__ void k_finalize(const float* __restrict__ pb1, const float* __restrict__ pw2,
                           const float* __restrict__ pb2, float* __restrict__ out) {
    const int b = blockIdx.x;
    const int t = threadIdx.x;
    float local = 0.f;
    for (int n = t; n < NH_; n += 128) {
        size_t o = (size_t)b * NH_ + n;
        float v = g_P[o] + g_P[(size_t)1 * B_ * NH_ + o] + g_P[(size_t)2 * B_ * NH_ + o] +
                  g_P[(size_t)3 * B_ * NH_ + o];
        v = fmaxf(v + pb1[n], 0.f);
        local += v * pw2[n];
    }
#pragma unroll
    for (int off = 16; off; off >>= 1) local += __shfl_down_sync(0xffffffffu, local, off);
    __shared__ float red[4];
    if ((t & 31) == 0) red[t >> 5] = local;
    __syncthreads();
    if (t == 0) {
        float s = red[0] + red[1] + red[2] + red[3] + pb2[0];
        out[b] = 1.f / (1.f + expf(-s));
    }
}

// ---------------- launch ----------------
extern "C" void kernel_launch(void* const* d_in, const int* in_sizes, int n_in,
                              void* d_out, int out_size) {
    const float* dense  = (const float*)d_in[0];
    const int*   sparse = (const int*)d_in[1];   // int32 on device
    /* d_in[2] tokenizers == arange(CARD): identity, unused */
    const float* emb = (const float*)d_in[3];
    const float* dw1 = (const float*)d_in[4];
    const float* db1 = (const float*)d_in[5];
    const float* dw2 = (const float*)d_in[6];
    const float* db2 = (const float*)d_in[7];
    const float* sw1 = (const float*)d_in[8];
    const float* sb1 = (const float*)d_in[9];
    const float* sw2 = (const float*)d_in[10];
    const float* sb2 = (const float*)d_in[11];
    const float* pw1 = (const float*)d_in[12];
    const float* pb1 = (const float*)d_in[13];
    const float* pw2 = (const float*)d_in[14];
    const float* pb2 = (const float*)d_in[15];
    float* out = (float*)d_out;

    cudaFuncSetAttribute(k_gemm, cudaFuncAttributeMaxDynamicSharedMemorySize, SMEM_BYTES);

    k_blocks<<<1, 256>>>();
    k_convert<<<NBLK_, 256>>>(pw1);
    k_features<<<B_, 64>>>(dense, sparse, emb, dw1, db1, dw2, db2, sw1, sb1, sw2, sb2);
    k_gemm<<<dim3(B_ / MT_, NH_ / NT_, KSPLIT_), 256, SMEM_BYTES>>>();
    k_finalize<<<B_, 128>>>(pb1, pw2, pb2, out);
}